// round 3
// baseline (speedup 1.0000x reference)
#include <cuda_runtime.h>

#define T_  256
#define B_  1024
#define NX_ 256
#define NY_ 64
#define NU_ 64
#define ND_ 32
#define TB_ (T_*B_)

// ---- device globals: transposed weights + stat accumulators (no allocs) ----
__device__ float  g_WxT[NX_*NX_];   // [k][j]
__device__ float  g_WuT[NU_*NX_];   // [k][j]
__device__ float  g_WdT[ND_*NX_];   // [k][j]
__device__ float  g_WyT[NX_*NY_];   // [k][j]
__device__ double g_acc[6];         // 0:sxmin 1:sxmax 2:sumin 3:sumax 4:sdx 5:dxd

// ---- packed fp32x2 helpers (Blackwell dual-FP32 pipe) ----
__device__ __forceinline__ unsigned long long pk2(float lo, float hi){
    unsigned long long r;
    asm("mov.b64 %0, {%1, %2};" : "=l"(r) : "f"(lo), "f"(hi));
    return r;
}
__device__ __forceinline__ void upk2(unsigned long long v, float& lo, float& hi){
    asm("mov.b64 {%0, %1}, %2;" : "=f"(lo), "=f"(hi) : "l"(v));
}
__device__ __forceinline__ unsigned long long fma2(unsigned long long a,
                                                   unsigned long long b,
                                                   unsigned long long c){
    unsigned long long d;
    asm("fma.rn.f32x2 %0, %1, %2, %3;" : "=l"(d) : "l"(a), "l"(b), "l"(c));
    return d;
}

__device__ __forceinline__ float warp_sum(float v){
    #pragma unroll
    for (int o = 16; o > 0; o >>= 1) v += __shfl_down_sync(0xffffffffu, v, o);
    return v;
}

// ============================================================================
// K0: transpose weights into [k][j] layout, zero accumulators
// ============================================================================
__global__ void k0_prep(const float* __restrict__ Wx, const float* __restrict__ Wu,
                        const float* __restrict__ Wd, const float* __restrict__ Wy){
    int tid = blockIdx.x * blockDim.x + threadIdx.x;
    int nt  = gridDim.x * blockDim.x;
    if (blockIdx.x == 0 && threadIdx.x < 6) g_acc[threadIdx.x] = 0.0;
    for (int i = tid; i < NX_*NX_; i += nt){ int j = i / NX_, k = i % NX_; g_WxT[k*NX_ + j] = Wx[i]; }
    for (int i = tid; i < NX_*NU_; i += nt){ int j = i / NU_, k = i % NU_; g_WuT[k*NX_ + j] = Wu[i]; }
    for (int i = tid; i < NX_*ND_; i += nt){ int j = i / ND_, k = i % ND_; g_WdT[k*NX_ + j] = Wd[i]; }
    for (int i = tid; i < NY_*NX_; i += nt){ int j = i / NX_, k = i % NX_; g_WyT[k*NY_ + j] = Wy[i]; }
}

// ============================================================================
// K1: S[t,b,:] = fu + fd + bx  written into the X output region.
//     fu = U@Wu^T + bu, fd = D@Wd^T + bd. Also accumulates fu/fd stats.
//     Block = 16 rows of (t*B+b), 256 threads (one output column each).
// ============================================================================
__global__ __launch_bounds__(256) void k1_fud(const float* __restrict__ U,
                                              const float* __restrict__ D,
                                              const float* __restrict__ bx,
                                              const float* __restrict__ bu,
                                              const float* __restrict__ bd,
                                              float* __restrict__ Xout){
    __shared__ __align__(16) float u_sT[NU_*16];   // [k][r]
    __shared__ __align__(16) float d_sT[ND_*16];   // [k][r]
    __shared__ float red[24];

    const int tid = threadIdx.x;
    const long g0 = (long)blockIdx.x * 16;

    for (int idx = tid; idx < 16*NU_; idx += 256){
        int r = idx >> 6, k = idx & 63;
        u_sT[k*16 + r] = U[(g0 + r)*NU_ + k];
    }
    for (int idx = tid; idx < 16*ND_; idx += 256){
        int r = idx >> 5, k = idx & 31;
        d_sT[k*16 + r] = D[(g0 + r)*ND_ + k];
    }
    __syncthreads();

    const int j = tid;
    const float buj = bu[j], bdj = bd[j], bxj = bx[j];
    unsigned long long au[8], ad[8];
    {
        unsigned long long b2u = pk2(buj, buj), b2d = pk2(bdj, bdj);
        #pragma unroll
        for (int p = 0; p < 8; p++){ au[p] = b2u; ad[p] = b2d; }
    }

    #pragma unroll 4
    for (int k = 0; k < NU_; k++){
        float w = __ldg(&g_WuT[k*NX_ + j]);
        unsigned long long w2 = pk2(w, w);
        const ulonglong2* xr = (const ulonglong2*)&u_sT[k*16];
        ulonglong2 q0 = xr[0], q1 = xr[1], q2 = xr[2], q3 = xr[3];
        au[0] = fma2(q0.x, w2, au[0]); au[1] = fma2(q0.y, w2, au[1]);
        au[2] = fma2(q1.x, w2, au[2]); au[3] = fma2(q1.y, w2, au[3]);
        au[4] = fma2(q2.x, w2, au[4]); au[5] = fma2(q2.y, w2, au[5]);
        au[6] = fma2(q3.x, w2, au[6]); au[7] = fma2(q3.y, w2, au[7]);
    }
    #pragma unroll 4
    for (int k = 0; k < ND_; k++){
        float w = __ldg(&g_WdT[k*NX_ + j]);
        unsigned long long w2 = pk2(w, w);
        const ulonglong2* xr = (const ulonglong2*)&d_sT[k*16];
        ulonglong2 q0 = xr[0], q1 = xr[1], q2 = xr[2], q3 = xr[3];
        ad[0] = fma2(q0.x, w2, ad[0]); ad[1] = fma2(q0.y, w2, ad[1]);
        ad[2] = fma2(q1.x, w2, ad[2]); ad[3] = fma2(q1.y, w2, ad[3]);
        ad[4] = fma2(q2.x, w2, ad[4]); ad[5] = fma2(q2.y, w2, ad[5]);
        ad[6] = fma2(q3.x, w2, ad[6]); ad[7] = fma2(q3.y, w2, ad[7]);
    }

    float s0 = 0.f, s1 = 0.f, s2 = 0.f;  // sumin, sumax, dxd
    #pragma unroll
    for (int p = 0; p < 8; p++){
        float fu0, fu1, fd0, fd1;
        upk2(au[p], fu0, fu1);
        upk2(ad[p], fd0, fd1);
        s0 += fmaxf(-fu0 - 1.f, 0.f) + fmaxf(-fu1 - 1.f, 0.f);
        s1 += fmaxf( fu0 - 1.f, 0.f) + fmaxf( fu1 - 1.f, 0.f);
        s2 += fmaxf(-fd0 - 1.f, 0.f) + fmaxf(fd0 - 1.f, 0.f)
            + fmaxf(-fd1 - 1.f, 0.f) + fmaxf(fd1 - 1.f, 0.f);
        Xout[(g0 + 2*p    )*NX_ + j] = fu0 + fd0 + bxj;
        Xout[(g0 + 2*p + 1)*NX_ + j] = fu1 + fd1 + bxj;
    }

    s0 = warp_sum(s0); s1 = warp_sum(s1); s2 = warp_sum(s2);
    int lane = tid & 31, w = tid >> 5;
    if (lane == 0){ red[w] = s0; red[8 + w] = s1; red[16 + w] = s2; }
    __syncthreads();
    if (tid == 0){
        float a = 0, b = 0, c = 0;
        #pragma unroll
        for (int i = 0; i < 8; i++){ a += red[i]; b += red[8 + i]; c += red[16 + i]; }
        atomicAdd(&g_acc[2], (double)a);
        atomicAdd(&g_acc[3], (double)b);
        atomicAdd(&g_acc[5], (double)c);
    }
}

// ============================================================================
// K2: sequential recurrence, independent per batch row.
//     128 CTAs x 8 rows. 256 threads = 128 column-pairs x 2 k-halves.
//     X[t] (holding S) is updated in place to xn. Accumulates xn stats.
// ============================================================================
__global__ __launch_bounds__(256) void k2_rec(const float* __restrict__ x0,
                                              float* __restrict__ Xout){
    __shared__ __align__(16) float xcT[NX_*8];   // [k][m]
    __shared__ __align__(16) float ps [8*NX_];   // kh==1 partials, [m][j]
    __shared__ float red[24];

    const int tid = threadIdx.x;
    const int kh  = tid >> 7;        // 0 or 1: which half of k
    const int j2  = tid & 127;       // column pair index
    const int c0  = j2 * 2;
    const long rb = (long)blockIdx.x * 8;

    for (int idx = tid; idx < 8*NX_; idx += 256){
        int m = idx >> 8, k = idx & 255;
        xcT[k*8 + m] = x0[(rb + m)*NX_ + k];
    }
    __syncthreads();

    float sxmin = 0.f, sxmax = 0.f, sdx = 0.f;

    for (int t = 0; t < T_; t++){
        float* Srow = Xout + ((long)t*B_ + rb)*NX_;

        float2 sv[8];
        if (kh == 0){
            #pragma unroll
            for (int m = 0; m < 8; m++) sv[m] = *(const float2*)&Srow[m*NX_ + c0];
        }

        unsigned long long a0[4] = {0,0,0,0}, a1[4] = {0,0,0,0};
        const float* wp = g_WxT + (kh*128)*NX_ + c0;
        const float* xp = xcT + (kh*128)*8;
        #pragma unroll 4
        for (int kk = 0; kk < 128; kk++){
            float2 w = *(const float2*)wp; wp += NX_;
            unsigned long long w20 = pk2(w.x, w.x);
            unsigned long long w21 = pk2(w.y, w.y);
            const ulonglong2* xr = (const ulonglong2*)xp; xp += 8;
            ulonglong2 q0 = xr[0], q1 = xr[1];
            a0[0] = fma2(q0.x, w20, a0[0]); a0[1] = fma2(q0.y, w20, a0[1]);
            a0[2] = fma2(q1.x, w20, a0[2]); a0[3] = fma2(q1.y, w20, a0[3]);
            a1[0] = fma2(q0.x, w21, a1[0]); a1[1] = fma2(q0.y, w21, a1[1]);
            a1[2] = fma2(q1.x, w21, a1[2]); a1[3] = fma2(q1.y, w21, a1[3]);
        }

        if (kh == 1){
            #pragma unroll
            for (int p = 0; p < 4; p++){
                float v00, v01, v10, v11;
                upk2(a0[p], v00, v01);  // col c0, rows 2p / 2p+1
                upk2(a1[p], v10, v11);  // col c1
                *(float2*)&ps[(2*p    )*NX_ + c0] = make_float2(v00, v10);
                *(float2*)&ps[(2*p + 1)*NX_ + c0] = make_float2(v01, v11);
            }
        }
        __syncthreads();

        if (kh == 0){
            float f0[8], f1[8];
            #pragma unroll
            for (int p = 0; p < 4; p++){
                upk2(a0[p], f0[2*p], f0[2*p+1]);
                upk2(a1[p], f1[2*p], f1[2*p+1]);
            }
            float4 oa = *(const float4*)&xcT[c0*8];
            float4 ob = *(const float4*)&xcT[c0*8 + 4];
            float4 oc = *(const float4*)&xcT[(c0+1)*8];
            float4 od = *(const float4*)&xcT[(c0+1)*8 + 4];
            float oc0[8] = {oa.x, oa.y, oa.z, oa.w, ob.x, ob.y, ob.z, ob.w};
            float oc1[8] = {oc.x, oc.y, oc.z, oc.w, od.x, od.y, od.z, od.w};
            float xn0[8], xn1[8];
            #pragma unroll
            for (int m = 0; m < 8; m++){
                float2 o = *(const float2*)&ps[m*NX_ + c0];
                float v0 = f0[m] + o.x + sv[m].x;
                float v1 = f1[m] + o.y + sv[m].y;
                sxmin += fmaxf(-v0 - 1.f, 0.f) + fmaxf(-v1 - 1.f, 0.f);
                sxmax += fmaxf( v0 - 1.f, 0.f) + fmaxf( v1 - 1.f, 0.f);
                float d0 = v0 - oc0[m], d1 = v1 - oc1[m];
                sdx += d0*d0 + d1*d1;
                *(float2*)&Srow[m*NX_ + c0] = make_float2(v0, v1);
                xn0[m] = v0; xn1[m] = v1;
            }
            *(float4*)&xcT[c0*8]       = make_float4(xn0[0], xn0[1], xn0[2], xn0[3]);
            *(float4*)&xcT[c0*8 + 4]   = make_float4(xn0[4], xn0[5], xn0[6], xn0[7]);
            *(float4*)&xcT[(c0+1)*8]   = make_float4(xn1[0], xn1[1], xn1[2], xn1[3]);
            *(float4*)&xcT[(c0+1)*8+4] = make_float4(xn1[4], xn1[5], xn1[6], xn1[7]);
        }
        __syncthreads();
    }

    sxmin = warp_sum(sxmin); sxmax = warp_sum(sxmax); sdx = warp_sum(sdx);
    int lane = tid & 31, w = tid >> 5;
    if (lane == 0){ red[w] = sxmin; red[8 + w] = sxmax; red[16 + w] = sdx; }
    __syncthreads();
    if (tid == 0){
        float a = 0, b = 0, c = 0;
        #pragma unroll
        for (int i = 0; i < 8; i++){ a += red[i]; b += red[8 + i]; c += red[16 + i]; }
        atomicAdd(&g_acc[0], (double)a);
        atomicAdd(&g_acc[1], (double)b);
        atomicAdd(&g_acc[4], (double)c);
    }
}

// ============================================================================
// K3: Y = X @ Wy^T + by. Block = 16 rows, 256 threads = 64 cols x 4 k-quarters.
// ============================================================================
__global__ __launch_bounds__(256) void k3_y(const float* __restrict__ Xout,
                                            const float* __restrict__ by,
                                            float* __restrict__ Yout){
    __shared__ __align__(16) float x_sT[NX_*16];      // [k][r]
    __shared__ __align__(16) float ps3[3*16*NY_];     // partials from kh=1..3
    const int tid = threadIdx.x;
    const int j   = tid & 63;
    const int kh  = tid >> 6;
    const long g0 = (long)blockIdx.x * 16;

    for (int idx = tid; idx < 16*NX_; idx += 256){
        int r = idx >> 8, k = idx & 255;
        x_sT[k*16 + r] = Xout[(g0 + r)*NX_ + k];
    }
    __syncthreads();

    unsigned long long acc[8] = {0,0,0,0,0,0,0,0};
    const float* wp = g_WyT + (kh*64)*NY_ + j;
    const float* xp = x_sT + (kh*64)*16;
    #pragma unroll 4
    for (int kk = 0; kk < 64; kk++){
        float w = __ldg(wp); wp += NY_;
        unsigned long long w2 = pk2(w, w);
        const ulonglong2* xr = (const ulonglong2*)xp; xp += 16;
        ulonglong2 q0 = xr[0], q1 = xr[1], q2 = xr[2], q3 = xr[3];
        acc[0] = fma2(q0.x, w2, acc[0]); acc[1] = fma2(q0.y, w2, acc[1]);
        acc[2] = fma2(q1.x, w2, acc[2]); acc[3] = fma2(q1.y, w2, acc[3]);
        acc[4] = fma2(q2.x, w2, acc[4]); acc[5] = fma2(q2.y, w2, acc[5]);
        acc[6] = fma2(q3.x, w2, acc[6]); acc[7] = fma2(q3.y, w2, acc[7]);
    }

    if (kh > 0){
        float* pbase = &ps3[(kh - 1)*16*NY_];
        #pragma unroll
        for (int p = 0; p < 8; p++){
            float lo, hi;
            upk2(acc[p], lo, hi);
            pbase[(2*p    )*NY_ + j] = lo;
            pbase[(2*p + 1)*NY_ + j] = hi;
        }
    }
    __syncthreads();
    if (kh == 0){
        float byj = by[j];
        #pragma unroll
        for (int p = 0; p < 8; p++){
            float lo, hi;
            upk2(acc[p], lo, hi);
            int m0 = 2*p, m1 = 2*p + 1;
            float v0 = lo + byj, v1 = hi + byj;
            #pragma unroll
            for (int q = 0; q < 3; q++){
                v0 += ps3[q*16*NY_ + m0*NY_ + j];
                v1 += ps3[q*16*NY_ + m1*NY_ + j];
            }
            Yout[(g0 + m0)*NY_ + j] = v0;
            Yout[(g0 + m1)*NY_ + j] = v1;
        }
    }
}

// ============================================================================
// K4: finalize reg_error = Q * sum(stat means); dx_u == sumin+sumax.
// ============================================================================
__global__ void k4_fin(float* __restrict__ out_reg){
    double inv = 1.0 / ((double)T_ * (double)B_ * (double)NX_);
    double s = g_acc[0] + g_acc[1] + 2.0*(g_acc[2] + g_acc[3]) + g_acc[4] + g_acc[5];
    *out_reg = (float)(0.2 * s * inv);
}

extern "C" void kernel_launch(void* const* d_in, const int* in_sizes, int n_in,
                              void* d_out, int out_size){
    const float* x  = (const float*)d_in[0];
    const float* U  = (const float*)d_in[1];
    const float* D  = (const float*)d_in[2];
    const float* Wx = (const float*)d_in[3];
    const float* bx = (const float*)d_in[4];
    const float* Wu = (const float*)d_in[5];
    const float* bu = (const float*)d_in[6];
    const float* Wd = (const float*)d_in[7];
    const float* bd = (const float*)d_in[8];
    const float* Wy = (const float*)d_in[9];
    const float* by = (const float*)d_in[10];

    float* out  = (float*)d_out;
    float* Xout = out;
    float* Yout = out + (size_t)TB_ * NX_;
    float* Rout = out + (size_t)TB_ * NX_ + (size_t)TB_ * NY_;

    k0_prep<<<256, 256>>>(Wx, Wu, Wd, Wy);
    k1_fud<<<TB_/16, 256>>>(U, D, bx, bu, bd, Xout);
    k2_rec<<<B_/8, 256>>>(x, Xout);
    k3_y<<<TB_/16, 256>>>(Xout, by, Yout);
    k4_fin<<<1, 1>>>(Rout);
}

// round 5
// speedup vs baseline: 1.3128x; 1.3128x over previous
#include <cuda_runtime.h>

#define T_  256
#define B_  1024
#define NX_ 256
#define NY_ 64
#define NU_ 64
#define ND_ 32
#define TB_ (T_*B_)

typedef unsigned long long ull;

// ---- device globals: transposed weights + stat accumulators (no allocs) ----
__device__ float  g_WxT [NX_*NX_];   // [k][j]
__device__ float  g_WudT[96*NX_];    // [k][j], k<64 = Wu-k, k>=64 = Wd-(k-64)
__device__ float  g_WyT [NX_*NY_];   // [k][j]
__device__ double g_acc[6];          // 0:sxmin 1:sxmax 2:sumin 3:sumax 4:sdx 5:dxd

// ---- packed fp32x2 helpers (Blackwell dual-FP32 pipe) ----
__device__ __forceinline__ ull pk2(float lo, float hi){
    ull r;
    asm("mov.b64 %0, {%1, %2};" : "=l"(r) : "f"(lo), "f"(hi));
    return r;
}
__device__ __forceinline__ void upk2(ull v, float& lo, float& hi){
    asm("mov.b64 {%0, %1}, %2;" : "=f"(lo), "=f"(hi) : "l"(v));
}
__device__ __forceinline__ ull fma2(ull a, ull b, ull c){
    ull d;
    asm("fma.rn.f32x2 %0, %1, %2, %3;" : "=l"(d) : "l"(a), "l"(b), "l"(c));
    return d;
}
__device__ __forceinline__ float warp_sum(float v){
    #pragma unroll
    for (int o = 16; o > 0; o >>= 1) v += __shfl_down_sync(0xffffffffu, v, o);
    return v;
}

// ============================================================================
// K0: build transposed/fused weight layouts, zero accumulators
// ============================================================================
__global__ void k0_prep(const float* __restrict__ Wx, const float* __restrict__ Wu,
                        const float* __restrict__ Wd, const float* __restrict__ Wy){
    int tid = blockIdx.x * blockDim.x + threadIdx.x;
    int nt  = gridDim.x * blockDim.x;
    if (blockIdx.x == 0 && threadIdx.x < 6) g_acc[threadIdx.x] = 0.0;
    for (int i = tid; i < NX_*NX_; i += nt){ int j = i / NX_, k = i % NX_; g_WxT[k*NX_ + j] = Wx[i]; }
    for (int i = tid; i < NX_*NU_; i += nt){ int j = i / NU_, k = i % NU_; g_WudT[k*NX_ + j] = Wu[i]; }
    for (int i = tid; i < NX_*ND_; i += nt){ int j = i / ND_, k = i % ND_; g_WudT[(64 + k)*NX_ + j] = Wd[i]; }
    for (int i = tid; i < NY_*NX_; i += nt){ int j = i / NX_, k = i % NX_; g_WyT[k*NY_ + j] = Wy[i]; }
}

// ============================================================================
// K1: S[t,b,:] = fu + fd + bx into the X output region, plus fu/fd stats.
//     Register-tiled GEMM: CTA = 128 rows x 64 cols, thread = 8r x 4c.
//     grid = (TB/128, 4). K = 96 (64 U + 32 D), stats split at k=64.
// ============================================================================
__global__ __launch_bounds__(256, 2) void k1_fud(const float* __restrict__ U,
                                                 const float* __restrict__ D,
                                                 const float* __restrict__ bx,
                                                 const float* __restrict__ bu,
                                                 const float* __restrict__ bd,
                                                 float* __restrict__ Xout){
    __shared__ __align__(16) float uds[96*132];   // [k][r], pad 132
    __shared__ float red[24];

    const int tid = threadIdx.x;
    const long g0 = (long)blockIdx.x * 128;
    const int cb  = blockIdx.y * 64;

    // stage U rows (k 0..63) and D rows (k 64..95), transposed [k][r]
    for (int idx = tid; idx < 128*64; idx += 256){
        int r = idx >> 6, k = idx & 63;
        uds[k*132 + r] = U[(g0 + r)*NU_ + k];
    }
    for (int idx = tid; idx < 128*32; idx += 256){
        int r = idx >> 5, k = idx & 31;
        uds[(64 + k)*132 + r] = D[(g0 + r)*ND_ + k];
    }
    __syncthreads();

    const int r0 = (tid >> 4) * 8;
    const int c0 = cb + (tid & 15) * 4;

    ull accu[16], accd[16];
    #pragma unroll
    for (int i = 0; i < 16; i++){ accu[i] = 0ull; accd[i] = 0ull; }

    const float* wb = g_WudT + c0;

    // ---- U part (k = 0..63) ----
    #pragma unroll 4
    for (int k = 0; k < 64; k++){
        float4 w = *(const float4*)(wb + k*NX_);
        ull w2[4] = { pk2(w.x, w.x), pk2(w.y, w.y), pk2(w.z, w.z), pk2(w.w, w.w) };
        ulonglong2 qa = *(const ulonglong2*)&uds[k*132 + r0];
        ulonglong2 qb = *(const ulonglong2*)&uds[k*132 + r0 + 4];
        #pragma unroll
        for (int c = 0; c < 4; c++){
            accu[c*4 + 0] = fma2(qa.x, w2[c], accu[c*4 + 0]);
            accu[c*4 + 1] = fma2(qa.y, w2[c], accu[c*4 + 1]);
            accu[c*4 + 2] = fma2(qb.x, w2[c], accu[c*4 + 2]);
            accu[c*4 + 3] = fma2(qb.y, w2[c], accu[c*4 + 3]);
        }
    }
    // ---- D part (k = 64..95) ----
    #pragma unroll 4
    for (int k = 64; k < 96; k++){
        float4 w = *(const float4*)(wb + k*NX_);
        ull w2[4] = { pk2(w.x, w.x), pk2(w.y, w.y), pk2(w.z, w.z), pk2(w.w, w.w) };
        ulonglong2 qa = *(const ulonglong2*)&uds[k*132 + r0];
        ulonglong2 qb = *(const ulonglong2*)&uds[k*132 + r0 + 4];
        #pragma unroll
        for (int c = 0; c < 4; c++){
            accd[c*4 + 0] = fma2(qa.x, w2[c], accd[c*4 + 0]);
            accd[c*4 + 1] = fma2(qa.y, w2[c], accd[c*4 + 1]);
            accd[c*4 + 2] = fma2(qb.x, w2[c], accd[c*4 + 2]);
            accd[c*4 + 3] = fma2(qb.y, w2[c], accd[c*4 + 3]);
        }
    }

    // ---- epilogue: biases, stats, store float4 per row ----
    float s0 = 0.f, s1 = 0.f, s2 = 0.f;  // sumin, sumax, dxd
    float vout[8][4];
    #pragma unroll
    for (int c = 0; c < 4; c++){
        float buc = bu[c0 + c], bdc = bd[c0 + c], bxc = bx[c0 + c];
        #pragma unroll
        for (int p = 0; p < 4; p++){
            float fu0, fu1, fd0, fd1;
            upk2(accu[c*4 + p], fu0, fu1);
            upk2(accd[c*4 + p], fd0, fd1);
            fu0 += buc; fu1 += buc; fd0 += bdc; fd1 += bdc;
            s0 += fmaxf(-fu0 - 1.f, 0.f) + fmaxf(-fu1 - 1.f, 0.f);
            s1 += fmaxf( fu0 - 1.f, 0.f) + fmaxf( fu1 - 1.f, 0.f);
            s2 += fmaxf(-fd0 - 1.f, 0.f) + fmaxf(fd0 - 1.f, 0.f)
                + fmaxf(-fd1 - 1.f, 0.f) + fmaxf(fd1 - 1.f, 0.f);
            vout[2*p    ][c] = fu0 + fd0 + bxc;
            vout[2*p + 1][c] = fu1 + fd1 + bxc;
        }
    }
    #pragma unroll
    for (int rr = 0; rr < 8; rr++){
        float4 o = make_float4(vout[rr][0], vout[rr][1], vout[rr][2], vout[rr][3]);
        *(float4*)&Xout[(g0 + r0 + rr)*NX_ + c0] = o;
    }

    s0 = warp_sum(s0); s1 = warp_sum(s1); s2 = warp_sum(s2);
    int lane = tid & 31, w = tid >> 5;
    if (lane == 0){ red[w] = s0; red[8 + w] = s1; red[16 + w] = s2; }
    __syncthreads();
    if (tid == 0){
        float a = 0, b = 0, c = 0;
        #pragma unroll
        for (int i = 0; i < 8; i++){ a += red[i]; b += red[8 + i]; c += red[16 + i]; }
        atomicAdd(&g_acc[2], (double)a);
        atomicAdd(&g_acc[3], (double)b);
        atomicAdd(&g_acc[5], (double)c);
    }
}

// ============================================================================
// K2: sequential recurrence, 128 CTAs x 8 rows, 256 threads = 128 col-pairs
//     x 2 k-halves. Software-pipelined inner loop (load-ahead 1 iteration,
//     final iteration peeled so the hot body has no predicated loads).
// ============================================================================
__global__ __launch_bounds__(256) void k2_rec(const float* __restrict__ x0,
                                              float* __restrict__ Xout){
    __shared__ __align__(16) float xcT[NX_*8];   // [k][m]
    __shared__ __align__(16) float ps [8*NX_];   // kh==1 partials, [m][j]
    __shared__ float red[24];

    const int tid = threadIdx.x;
    const int kh  = tid >> 7;
    const int j2  = tid & 127;
    const int c0  = j2 * 2;
    const long rb = (long)blockIdx.x * 8;

    for (int idx = tid; idx < 8*NX_; idx += 256){
        int m = idx >> 8, k = idx & 255;
        xcT[k*8 + m] = x0[(rb + m)*NX_ + k];
    }
    __syncthreads();

    float sxmin = 0.f, sxmax = 0.f, sdx = 0.f;

    for (int t = 0; t < T_; t++){
        float* Srow = Xout + ((long)t*B_ + rb)*NX_;

        float2 sv[8];
        if (kh == 0){
            #pragma unroll
            for (int m = 0; m < 8; m++) sv[m] = *(const float2*)&Srow[m*NX_ + c0];
        }

        ull a0[4] = {0,0,0,0}, a1[4] = {0,0,0,0};
        const float* wp = g_WxT + (kh*128)*NX_ + c0;
        const ulonglong2* xp = (const ulonglong2*)(xcT + (kh*128)*8);

        float2 w = *(const float2*)wp;
        ulonglong2 q0 = xp[0];
        ulonglong2 q1 = xp[1];
        #pragma unroll 8
        for (int kk = 0; kk < 127; kk++){
            float2 wn       = *(const float2*)(wp + NX_);
            ulonglong2 q0n  = xp[2];
            ulonglong2 q1n  = xp[3];
            ull w20 = pk2(w.x, w.x);
            ull w21 = pk2(w.y, w.y);
            a0[0] = fma2(q0.x, w20, a0[0]); a0[1] = fma2(q0.y, w20, a0[1]);
            a0[2] = fma2(q1.x, w20, a0[2]); a0[3] = fma2(q1.y, w20, a0[3]);
            a1[0] = fma2(q0.x, w21, a1[0]); a1[1] = fma2(q0.y, w21, a1[1]);
            a1[2] = fma2(q1.x, w21, a1[2]); a1[3] = fma2(q1.y, w21, a1[3]);
            w = wn; q0 = q0n; q1 = q1n; wp += NX_; xp += 2;
        }
        {   // peeled last iteration (no prefetch)
            ull w20 = pk2(w.x, w.x);
            ull w21 = pk2(w.y, w.y);
            a0[0] = fma2(q0.x, w20, a0[0]); a0[1] = fma2(q0.y, w20, a0[1]);
            a0[2] = fma2(q1.x, w20, a0[2]); a0[3] = fma2(q1.y, w20, a0[3]);
            a1[0] = fma2(q0.x, w21, a1[0]); a1[1] = fma2(q0.y, w21, a1[1]);
            a1[2] = fma2(q1.x, w21, a1[2]); a1[3] = fma2(q1.y, w21, a1[3]);
        }

        if (kh == 1){
            #pragma unroll
            for (int p = 0; p < 4; p++){
                float v00, v01, v10, v11;
                upk2(a0[p], v00, v01);
                upk2(a1[p], v10, v11);
                *(float2*)&ps[(2*p    )*NX_ + c0] = make_float2(v00, v10);
                *(float2*)&ps[(2*p + 1)*NX_ + c0] = make_float2(v01, v11);
            }
        }
        __syncthreads();

        if (kh == 0){
            float f0[8], f1[8];
            #pragma unroll
            for (int p = 0; p < 4; p++){
                upk2(a0[p], f0[2*p], f0[2*p+1]);
                upk2(a1[p], f1[2*p], f1[2*p+1]);
            }
            float4 oa = *(const float4*)&xcT[c0*8];
            float4 ob = *(const float4*)&xcT[c0*8 + 4];
            float4 oc = *(const float4*)&xcT[(c0+1)*8];
            float4 od = *(const float4*)&xcT[(c0+1)*8 + 4];
            float oc0[8] = {oa.x, oa.y, oa.z, oa.w, ob.x, ob.y, ob.z, ob.w};
            float oc1[8] = {oc.x, oc.y, oc.z, oc.w, od.x, od.y, od.z, od.w};
            float xn0[8], xn1[8];
            #pragma unroll
            for (int m = 0; m < 8; m++){
                float2 o = *(const float2*)&ps[m*NX_ + c0];
                float v0 = f0[m] + o.x + sv[m].x;
                float v1 = f1[m] + o.y + sv[m].y;
                sxmin += fmaxf(-v0 - 1.f, 0.f) + fmaxf(-v1 - 1.f, 0.f);
                sxmax += fmaxf( v0 - 1.f, 0.f) + fmaxf( v1 - 1.f, 0.f);
                float d0 = v0 - oc0[m], d1 = v1 - oc1[m];
                sdx += d0*d0 + d1*d1;
                *(float2*)&Srow[m*NX_ + c0] = make_float2(v0, v1);
                xn0[m] = v0; xn1[m] = v1;
            }
            *(float4*)&xcT[c0*8]       = make_float4(xn0[0], xn0[1], xn0[2], xn0[3]);
            *(float4*)&xcT[c0*8 + 4]   = make_float4(xn0[4], xn0[5], xn0[6], xn0[7]);
            *(float4*)&xcT[(c0+1)*8]   = make_float4(xn1[0], xn1[1], xn1[2], xn1[3]);
            *(float4*)&xcT[(c0+1)*8+4] = make_float4(xn1[4], xn1[5], xn1[6], xn1[7]);
        }
        __syncthreads();
    }

    sxmin = warp_sum(sxmin); sxmax = warp_sum(sxmax); sdx = warp_sum(sdx);
    int lane = tid & 31, w = tid >> 5;
    if (lane == 0){ red[w] = sxmin; red[8 + w] = sxmax; red[16 + w] = sdx; }
    __syncthreads();
    if (tid == 0){
        float a = 0, b = 0, c = 0;
        #pragma unroll
        for (int i = 0; i < 8; i++){ a += red[i]; b += red[8 + i]; c += red[16 + i]; }
        atomicAdd(&g_acc[0], (double)a);
        atomicAdd(&g_acc[1], (double)b);
        atomicAdd(&g_acc[4], (double)c);
    }
}

// ============================================================================
// K3: Y = X @ Wy^T + by. Register-tiled: CTA = 128 rows x 64 cols (full NY),
//     thread = 8r x 4c, K = 256 staged in 4 chunks of 64.
// ============================================================================
__global__ __launch_bounds__(256) void k3_y(const float* __restrict__ Xout,
                                            const float* __restrict__ by,
                                            float* __restrict__ Yout){
    __shared__ __align__(16) float xs[64*132];   // [k][r], pad 132
    const int tid = threadIdx.x;
    const long g0 = (long)blockIdx.x * 128;
    const int r0 = (tid >> 4) * 8;
    const int c0 = (tid & 15) * 4;

    ull acc[16];
    #pragma unroll
    for (int i = 0; i < 16; i++) acc[i] = 0ull;

    for (int ch = 0; ch < 4; ch++){
        if (ch) __syncthreads();
        for (int idx = tid; idx < 128*64; idx += 256){
            int r = idx >> 6, k = idx & 63;
            xs[k*132 + r] = Xout[(g0 + r)*NX_ + ch*64 + k];
        }
        __syncthreads();

        const float* wb = g_WyT + (ch*64)*NY_ + c0;
        #pragma unroll 4
        for (int k = 0; k < 64; k++){
            float4 w = *(const float4*)(wb + k*NY_);
            ull w2[4] = { pk2(w.x, w.x), pk2(w.y, w.y), pk2(w.z, w.z), pk2(w.w, w.w) };
            ulonglong2 qa = *(const ulonglong2*)&xs[k*132 + r0];
            ulonglong2 qb = *(const ulonglong2*)&xs[k*132 + r0 + 4];
            #pragma unroll
            for (int c = 0; c < 4; c++){
                acc[c*4 + 0] = fma2(qa.x, w2[c], acc[c*4 + 0]);
                acc[c*4 + 1] = fma2(qa.y, w2[c], acc[c*4 + 1]);
                acc[c*4 + 2] = fma2(qb.x, w2[c], acc[c*4 + 2]);
                acc[c*4 + 3] = fma2(qb.y, w2[c], acc[c*4 + 3]);
            }
        }
    }

    float byv[4] = { by[c0], by[c0+1], by[c0+2], by[c0+3] };
    float vout[8][4];
    #pragma unroll
    for (int c = 0; c < 4; c++){
        #pragma unroll
        for (int p = 0; p < 4; p++){
            float lo, hi;
            upk2(acc[c*4 + p], lo, hi);
            vout[2*p    ][c] = lo + byv[c];
            vout[2*p + 1][c] = hi + byv[c];
        }
    }
    #pragma unroll
    for (int rr = 0; rr < 8; rr++){
        float4 o = make_float4(vout[rr][0], vout[rr][1], vout[rr][2], vout[rr][3]);
        *(float4*)&Yout[(g0 + r0 + rr)*NY_ + c0] = o;
    }
}

// ============================================================================
// K4: finalize reg_error = Q * sum(stat means); dx_u == sumin+sumax.
// ============================================================================
__global__ void k4_fin(float* __restrict__ out_reg){
    double inv = 1.0 / ((double)T_ * (double)B_ * (double)NX_);
    double s = g_acc[0] + g_acc[1] + 2.0*(g_acc[2] + g_acc[3]) + g_acc[4] + g_acc[5];
    *out_reg = (float)(0.2 * s * inv);
}

extern "C" void kernel_launch(void* const* d_in, const int* in_sizes, int n_in,
                              void* d_out, int out_size){
    const float* x  = (const float*)d_in[0];
    const float* U  = (const float*)d_in[1];
    const float* D  = (const float*)d_in[2];
    const float* Wx = (const float*)d_in[3];
    const float* bx = (const float*)d_in[4];
    const float* Wu = (const float*)d_in[5];
    const float* bu = (const float*)d_in[6];
    const float* Wd = (const float*)d_in[7];
    const float* bd = (const float*)d_in[8];
    const float* Wy = (const float*)d_in[9];
    const float* by = (const float*)d_in[10];

    float* out  = (float*)d_out;
    float* Xout = out;
    float* Yout = out + (size_t)TB_ * NX_;
    float* Rout = out + (size_t)TB_ * NX_ + (size_t)TB_ * NY_;

    k0_prep<<<256, 256>>>(Wx, Wu, Wd, Wy);
    k1_fud<<<dim3(TB_/128, 4), 256>>>(U, D, bx, bu, bd, Xout);
    k2_rec<<<B_/8, 256>>>(x, Xout);
    k3_y<<<TB_/128, 256>>>(Xout, by, Yout);
    k4_fin<<<1, 1>>>(Rout);
}

// round 6
// speedup vs baseline: 1.6590x; 1.2637x over previous
#include <cuda_runtime.h>

#define T_  256
#define B_  1024
#define NX_ 256
#define NY_ 64
#define NU_ 64
#define ND_ 32
#define TB_ (T_*B_)

typedef unsigned long long ull;

// ---- device globals: transposed weights + stat accumulators (no allocs) ----
__device__ float  g_WxT [NX_*NX_];   // [k][j]
__device__ float  g_WudT[96*NX_];    // [k][j], k<64 = Wu-k, k>=64 = Wd-(k-64)
__device__ float  g_WyT [NX_*NY_];   // [k][j]
__device__ double g_acc[6];          // 0:sxmin 1:sxmax 2:sumin 3:sumax 4:sdx 5:dxd

// ---- packed fp32x2 helpers (Blackwell dual-FP32 pipe) ----
__device__ __forceinline__ ull pk2(float lo, float hi){
    ull r;
    asm("mov.b64 %0, {%1, %2};" : "=l"(r) : "f"(lo), "f"(hi));
    return r;
}
__device__ __forceinline__ void upk2(ull v, float& lo, float& hi){
    asm("mov.b64 {%0, %1}, %2;" : "=f"(lo), "=f"(hi) : "l"(v));
}
__device__ __forceinline__ ull fma2(ull a, ull b, ull c){
    ull d;
    asm("fma.rn.f32x2 %0, %1, %2, %3;" : "=l"(d) : "l"(a), "l"(b), "l"(c));
    return d;
}
__device__ __forceinline__ float warp_sum(float v){
    #pragma unroll
    for (int o = 16; o > 0; o >>= 1) v += __shfl_down_sync(0xffffffffu, v, o);
    return v;
}

// ============================================================================
// K0: build transposed/fused weight layouts, zero accumulators
// ============================================================================
__global__ void k0_prep(const float* __restrict__ Wx, const float* __restrict__ Wu,
                        const float* __restrict__ Wd, const float* __restrict__ Wy){
    int tid = blockIdx.x * blockDim.x + threadIdx.x;
    int nt  = gridDim.x * blockDim.x;
    if (blockIdx.x == 0 && threadIdx.x < 6) g_acc[threadIdx.x] = 0.0;
    for (int i = tid; i < NX_*NX_; i += nt){ int j = i / NX_, k = i % NX_; g_WxT[k*NX_ + j] = Wx[i]; }
    for (int i = tid; i < NX_*NU_; i += nt){ int j = i / NU_, k = i % NU_; g_WudT[k*NX_ + j] = Wu[i]; }
    for (int i = tid; i < NX_*ND_; i += nt){ int j = i / ND_, k = i % ND_; g_WudT[(64 + k)*NX_ + j] = Wd[i]; }
    for (int i = tid; i < NY_*NX_; i += nt){ int j = i / NX_, k = i % NX_; g_WyT[k*NY_ + j] = Wy[i]; }
}

// ============================================================================
// K1: S[t,b,:] = fu + fd + bx into the X output region, plus fu/fd stats.
//     Register-tiled GEMM: CTA = 128 rows x 64 cols, thread = 8r x 4c.
//     grid = (TB/128, 4). K = 96 (64 U + 32 D), stats split at k=64.
// ============================================================================
__global__ __launch_bounds__(256, 2) void k1_fud(const float* __restrict__ U,
                                                 const float* __restrict__ D,
                                                 const float* __restrict__ bx,
                                                 const float* __restrict__ bu,
                                                 const float* __restrict__ bd,
                                                 float* __restrict__ Xout){
    __shared__ __align__(16) float uds[96*132];   // [k][r], pad 132
    __shared__ float red[24];

    const int tid = threadIdx.x;
    const long g0 = (long)blockIdx.x * 128;
    const int cb  = blockIdx.y * 64;

    // stage U rows (k 0..63) and D rows (k 64..95), transposed [k][r]
    for (int idx = tid; idx < 128*64; idx += 256){
        int r = idx >> 6, k = idx & 63;
        uds[k*132 + r] = U[(g0 + r)*NU_ + k];
    }
    for (int idx = tid; idx < 128*32; idx += 256){
        int r = idx >> 5, k = idx & 31;
        uds[(64 + k)*132 + r] = D[(g0 + r)*ND_ + k];
    }
    __syncthreads();

    const int r0 = (tid >> 4) * 8;
    const int c0 = cb + (tid & 15) * 4;

    ull accu[16], accd[16];
    #pragma unroll
    for (int i = 0; i < 16; i++){ accu[i] = 0ull; accd[i] = 0ull; }

    const float* wb = g_WudT + c0;

    // ---- U part (k = 0..63) ----
    #pragma unroll 4
    for (int k = 0; k < 64; k++){
        float4 w = *(const float4*)(wb + k*NX_);
        ull w2[4] = { pk2(w.x, w.x), pk2(w.y, w.y), pk2(w.z, w.z), pk2(w.w, w.w) };
        ulonglong2 qa = *(const ulonglong2*)&uds[k*132 + r0];
        ulonglong2 qb = *(const ulonglong2*)&uds[k*132 + r0 + 4];
        #pragma unroll
        for (int c = 0; c < 4; c++){
            accu[c*4 + 0] = fma2(qa.x, w2[c], accu[c*4 + 0]);
            accu[c*4 + 1] = fma2(qa.y, w2[c], accu[c*4 + 1]);
            accu[c*4 + 2] = fma2(qb.x, w2[c], accu[c*4 + 2]);
            accu[c*4 + 3] = fma2(qb.y, w2[c], accu[c*4 + 3]);
        }
    }
    // ---- D part (k = 64..95) ----
    #pragma unroll 4
    for (int k = 64; k < 96; k++){
        float4 w = *(const float4*)(wb + k*NX_);
        ull w2[4] = { pk2(w.x, w.x), pk2(w.y, w.y), pk2(w.z, w.z), pk2(w.w, w.w) };
        ulonglong2 qa = *(const ulonglong2*)&uds[k*132 + r0];
        ulonglong2 qb = *(const ulonglong2*)&uds[k*132 + r0 + 4];
        #pragma unroll
        for (int c = 0; c < 4; c++){
            accd[c*4 + 0] = fma2(qa.x, w2[c], accd[c*4 + 0]);
            accd[c*4 + 1] = fma2(qa.y, w2[c], accd[c*4 + 1]);
            accd[c*4 + 2] = fma2(qb.x, w2[c], accd[c*4 + 2]);
            accd[c*4 + 3] = fma2(qb.y, w2[c], accd[c*4 + 3]);
        }
    }

    // ---- epilogue: biases, stats, store float4 per row ----
    float s0 = 0.f, s1 = 0.f, s2 = 0.f;  // sumin, sumax, dxd
    float vout[8][4];
    #pragma unroll
    for (int c = 0; c < 4; c++){
        float buc = bu[c0 + c], bdc = bd[c0 + c], bxc = bx[c0 + c];
        #pragma unroll
        for (int p = 0; p < 4; p++){
            float fu0, fu1, fd0, fd1;
            upk2(accu[c*4 + p], fu0, fu1);
            upk2(accd[c*4 + p], fd0, fd1);
            fu0 += buc; fu1 += buc; fd0 += bdc; fd1 += bdc;
            s0 += fmaxf(-fu0 - 1.f, 0.f) + fmaxf(-fu1 - 1.f, 0.f);
            s1 += fmaxf( fu0 - 1.f, 0.f) + fmaxf( fu1 - 1.f, 0.f);
            s2 += fmaxf(-fd0 - 1.f, 0.f) + fmaxf(fd0 - 1.f, 0.f)
                + fmaxf(-fd1 - 1.f, 0.f) + fmaxf(fd1 - 1.f, 0.f);
            vout[2*p    ][c] = fu0 + fd0 + bxc;
            vout[2*p + 1][c] = fu1 + fd1 + bxc;
        }
    }
    #pragma unroll
    for (int rr = 0; rr < 8; rr++){
        float4 o = make_float4(vout[rr][0], vout[rr][1], vout[rr][2], vout[rr][3]);
        *(float4*)&Xout[(g0 + r0 + rr)*NX_ + c0] = o;
    }

    s0 = warp_sum(s0); s1 = warp_sum(s1); s2 = warp_sum(s2);
    int lane = tid & 31, w = tid >> 5;
    if (lane == 0){ red[w] = s0; red[8 + w] = s1; red[16 + w] = s2; }
    __syncthreads();
    if (tid == 0){
        float a = 0, b = 0, c = 0;
        #pragma unroll
        for (int i = 0; i < 8; i++){ a += red[i]; b += red[8 + i]; c += red[16 + i]; }
        atomicAdd(&g_acc[2], (double)a);
        atomicAdd(&g_acc[3], (double)b);
        atomicAdd(&g_acc[5], (double)c);
    }
}

// ============================================================================
// K2: sequential recurrence, 128 CTAs x 8 rows, 256 threads = 128 col-pairs
//     x 2 k-halves. Inner loop blocked 16x8 with all loads batched at block
//     top -> MLP~8 on the global weight stream (was MLP~1, the bottleneck).
// ============================================================================
__global__ __launch_bounds__(256) void k2_rec(const float* __restrict__ x0,
                                              float* __restrict__ Xout){
    __shared__ __align__(16) float xcT[NX_*8];   // [k][m]
    __shared__ __align__(16) float ps [8*NX_];   // kh==1 partials, [m][j]
    __shared__ float red[24];

    const int tid = threadIdx.x;
    const int kh  = tid >> 7;
    const int j2  = tid & 127;
    const int c0  = j2 * 2;
    const long rb = (long)blockIdx.x * 8;

    for (int idx = tid; idx < 8*NX_; idx += 256){
        int m = idx >> 8, k = idx & 255;
        xcT[k*8 + m] = x0[(rb + m)*NX_ + k];
    }
    __syncthreads();

    float sxmin = 0.f, sxmax = 0.f, sdx = 0.f;

    for (int t = 0; t < T_; t++){
        float* Srow = Xout + ((long)t*B_ + rb)*NX_;

        float2 sv[8];
        if (kh == 0){
            #pragma unroll
            for (int m = 0; m < 8; m++) sv[m] = *(const float2*)&Srow[m*NX_ + c0];
        }

        ull a0[4] = {0,0,0,0}, a1[4] = {0,0,0,0};
        const float* wp = g_WxT + (kh*128)*NX_ + c0;
        const ulonglong2* xp = (const ulonglong2*)(xcT + (kh*128)*8);

        #pragma unroll 1
        for (int kb = 0; kb < 16; kb++){
            // batch all loads for this 8-k block (front-hoisted -> MLP=8)
            float2 w8[8]; ulonglong2 qa[8], qb[8];
            #pragma unroll
            for (int i = 0; i < 8; i++){
                w8[i] = *(const float2*)(wp + i*NX_);
                qa[i] = xp[2*i];
                qb[i] = xp[2*i + 1];
            }
            #pragma unroll
            for (int i = 0; i < 8; i++){
                ull w20 = pk2(w8[i].x, w8[i].x);
                ull w21 = pk2(w8[i].y, w8[i].y);
                a0[0] = fma2(qa[i].x, w20, a0[0]); a0[1] = fma2(qa[i].y, w20, a0[1]);
                a0[2] = fma2(qb[i].x, w20, a0[2]); a0[3] = fma2(qb[i].y, w20, a0[3]);
                a1[0] = fma2(qa[i].x, w21, a1[0]); a1[1] = fma2(qa[i].y, w21, a1[1]);
                a1[2] = fma2(qb[i].x, w21, a1[2]); a1[3] = fma2(qb[i].y, w21, a1[3]);
            }
            wp += 8*NX_;
            xp += 16;
        }

        if (kh == 1){
            #pragma unroll
            for (int p = 0; p < 4; p++){
                float v00, v01, v10, v11;
                upk2(a0[p], v00, v01);
                upk2(a1[p], v10, v11);
                *(float2*)&ps[(2*p    )*NX_ + c0] = make_float2(v00, v10);
                *(float2*)&ps[(2*p + 1)*NX_ + c0] = make_float2(v01, v11);
            }
        }
        __syncthreads();

        if (kh == 0){
            float f0[8], f1[8];
            #pragma unroll
            for (int p = 0; p < 4; p++){
                upk2(a0[p], f0[2*p], f0[2*p+1]);
                upk2(a1[p], f1[2*p], f1[2*p+1]);
            }
            float4 oa = *(const float4*)&xcT[c0*8];
            float4 ob = *(const float4*)&xcT[c0*8 + 4];
            float4 oc = *(const float4*)&xcT[(c0+1)*8];
            float4 od = *(const float4*)&xcT[(c0+1)*8 + 4];
            float oc0[8] = {oa.x, oa.y, oa.z, oa.w, ob.x, ob.y, ob.z, ob.w};
            float oc1[8] = {oc.x, oc.y, oc.z, oc.w, od.x, od.y, od.z, od.w};
            float xn0[8], xn1[8];
            #pragma unroll
            for (int m = 0; m < 8; m++){
                float2 o = *(const float2*)&ps[m*NX_ + c0];
                float v0 = f0[m] + o.x + sv[m].x;
                float v1 = f1[m] + o.y + sv[m].y;
                sxmin += fmaxf(-v0 - 1.f, 0.f) + fmaxf(-v1 - 1.f, 0.f);
                sxmax += fmaxf( v0 - 1.f, 0.f) + fmaxf( v1 - 1.f, 0.f);
                float d0 = v0 - oc0[m], d1 = v1 - oc1[m];
                sdx += d0*d0 + d1*d1;
                *(float2*)&Srow[m*NX_ + c0] = make_float2(v0, v1);
                xn0[m] = v0; xn1[m] = v1;
            }
            *(float4*)&xcT[c0*8]       = make_float4(xn0[0], xn0[1], xn0[2], xn0[3]);
            *(float4*)&xcT[c0*8 + 4]   = make_float4(xn0[4], xn0[5], xn0[6], xn0[7]);
            *(float4*)&xcT[(c0+1)*8]   = make_float4(xn1[0], xn1[1], xn1[2], xn1[3]);
            *(float4*)&xcT[(c0+1)*8+4] = make_float4(xn1[4], xn1[5], xn1[6], xn1[7]);
        }
        __syncthreads();
    }

    sxmin = warp_sum(sxmin); sxmax = warp_sum(sxmax); sdx = warp_sum(sdx);
    int lane = tid & 31, w = tid >> 5;
    if (lane == 0){ red[w] = sxmin; red[8 + w] = sxmax; red[16 + w] = sdx; }
    __syncthreads();
    if (tid == 0){
        float a = 0, b = 0, c = 0;
        #pragma unroll
        for (int i = 0; i < 8; i++){ a += red[i]; b += red[8 + i]; c += red[16 + i]; }
        atomicAdd(&g_acc[0], (double)a);
        atomicAdd(&g_acc[1], (double)b);
        atomicAdd(&g_acc[4], (double)c);
    }
}

// ============================================================================
// K3: Y = X @ Wy^T + by. Register-tiled: CTA = 128 rows x 64 cols (full NY),
//     thread = 8r x 4c, K = 256 staged in 4 chunks of 64.
// ============================================================================
__global__ __launch_bounds__(256) void k3_y(const float* __restrict__ Xout,
                                            const float* __restrict__ by,
                                            float* __restrict__ Yout){
    __shared__ __align__(16) float xs[64*132];   // [k][r], pad 132
    const int tid = threadIdx.x;
    const long g0 = (long)blockIdx.x * 128;
    const int r0 = (tid >> 4) * 8;
    const int c0 = (tid & 15) * 4;

    ull acc[16];
    #pragma unroll
    for (int i = 0; i < 16; i++) acc[i] = 0ull;

    for (int ch = 0; ch < 4; ch++){
        if (ch) __syncthreads();
        for (int idx = tid; idx < 128*64; idx += 256){
            int r = idx >> 6, k = idx & 63;
            xs[k*132 + r] = Xout[(g0 + r)*NX_ + ch*64 + k];
        }
        __syncthreads();

        const float* wb = g_WyT + (ch*64)*NY_ + c0;
        #pragma unroll 4
        for (int k = 0; k < 64; k++){
            float4 w = *(const float4*)(wb + k*NY_);
            ull w2[4] = { pk2(w.x, w.x), pk2(w.y, w.y), pk2(w.z, w.z), pk2(w.w, w.w) };
            ulonglong2 qa = *(const ulonglong2*)&xs[k*132 + r0];
            ulonglong2 qb = *(const ulonglong2*)&xs[k*132 + r0 + 4];
            #pragma unroll
            for (int c = 0; c < 4; c++){
                acc[c*4 + 0] = fma2(qa.x, w2[c], acc[c*4 + 0]);
                acc[c*4 + 1] = fma2(qa.y, w2[c], acc[c*4 + 1]);
                acc[c*4 + 2] = fma2(qb.x, w2[c], acc[c*4 + 2]);
                acc[c*4 + 3] = fma2(qb.y, w2[c], acc[c*4 + 3]);
            }
        }
    }

    float byv[4] = { by[c0], by[c0+1], by[c0+2], by[c0+3] };
    float vout[8][4];
    #pragma unroll
    for (int c = 0; c < 4; c++){
        #pragma unroll
        for (int p = 0; p < 4; p++){
            float lo, hi;
            upk2(acc[c*4 + p], lo, hi);
            vout[2*p    ][c] = lo + byv[c];
            vout[2*p + 1][c] = hi + byv[c];
        }
    }
    #pragma unroll
    for (int rr = 0; rr < 8; rr++){
        float4 o = make_float4(vout[rr][0], vout[rr][1], vout[rr][2], vout[rr][3]);
        *(float4*)&Yout[(g0 + r0 + rr)*NY_ + c0] = o;
    }
}

// ============================================================================
// K4: finalize reg_error = Q * sum(stat means); dx_u == sumin+sumax.
// ============================================================================
__global__ void k4_fin(float* __restrict__ out_reg){
    double inv = 1.0 / ((double)T_ * (double)B_ * (double)NX_);
    double s = g_acc[0] + g_acc[1] + 2.0*(g_acc[2] + g_acc[3]) + g_acc[4] + g_acc[5];
    *out_reg = (float)(0.2 * s * inv);
}

extern "C" void kernel_launch(void* const* d_in, const int* in_sizes, int n_in,
                              void* d_out, int out_size){
    const float* x  = (const float*)d_in[0];
    const float* U  = (const float*)d_in[1];
    const float* D  = (const float*)d_in[2];
    const float* Wx = (const float*)d_in[3];
    const float* bx = (const float*)d_in[4];
    const float* Wu = (const float*)d_in[5];
    const float* bu = (const float*)d_in[6];
    const float* Wd = (const float*)d_in[7];
    const float* bd = (const float*)d_in[8];
    const float* Wy = (const float*)d_in[9];
    const float* by = (const float*)d_in[10];

    float* out  = (float*)d_out;
    float* Xout = out;
    float* Yout = out + (size_t)TB_ * NX_;
    float* Rout = out + (size_t)TB_ * NX_ + (size_t)TB_ * NY_;

    k0_prep<<<256, 256>>>(Wx, Wu, Wd, Wy);
    k1_fud<<<dim3(TB_/128, 4), 256>>>(U, D, bx, bu, bd, Xout);
    k2_rec<<<B_/8, 256>>>(x, Xout);
    k3_y<<<TB_/128, 256>>>(Xout, by, Yout);
    k4_fin<<<1, 1>>>(Rout);
}

// round 7
// speedup vs baseline: 2.1572x; 1.3003x over previous
#include <cuda_runtime.h>

#define T_  256
#define B_  1024
#define NX_ 256
#define NY_ 64
#define NU_ 64
#define ND_ 32
#define TB_ (T_*B_)

typedef unsigned long long ull;

// ---- device globals: transposed weights + stat accumulators (no allocs) ----
__device__ float  g_WxT [NX_*NX_];   // [k][j]
__device__ float  g_WudT[96*NX_];    // [k][j], k<64 = Wu-k, k>=64 = Wd-(k-64)
__device__ float  g_WyT [NX_*NY_];   // [k][j]
__device__ double g_acc[6];          // 0:sxmin 1:sxmax 2:sumin 3:sumax 4:sdx 5:dxd

// ---- packed fp32x2 helpers (Blackwell dual-FP32 pipe) ----
__device__ __forceinline__ ull pk2(float lo, float hi){
    ull r;
    asm("mov.b64 %0, {%1, %2};" : "=l"(r) : "f"(lo), "f"(hi));
    return r;
}
__device__ __forceinline__ void upk2(ull v, float& lo, float& hi){
    asm("mov.b64 {%0, %1}, %2;" : "=f"(lo), "=f"(hi) : "l"(v));
}
__device__ __forceinline__ ull fma2(ull a, ull b, ull c){
    ull d;
    asm("fma.rn.f32x2 %0, %1, %2, %3;" : "=l"(d) : "l"(a), "l"(b), "l"(c));
    return d;
}
__device__ __forceinline__ float warp_sum(float v){
    #pragma unroll
    for (int o = 16; o > 0; o >>= 1) v += __shfl_down_sync(0xffffffffu, v, o);
    return v;
}

// ============================================================================
// K0: build transposed/fused weight layouts, zero accumulators
// ============================================================================
__global__ void k0_prep(const float* __restrict__ Wx, const float* __restrict__ Wu,
                        const float* __restrict__ Wd, const float* __restrict__ Wy){
    int tid = blockIdx.x * blockDim.x + threadIdx.x;
    int nt  = gridDim.x * blockDim.x;
    if (blockIdx.x == 0 && threadIdx.x < 6) g_acc[threadIdx.x] = 0.0;
    for (int i = tid; i < NX_*NX_; i += nt){ int j = i / NX_, k = i % NX_; g_WxT[k*NX_ + j] = Wx[i]; }
    for (int i = tid; i < NX_*NU_; i += nt){ int j = i / NU_, k = i % NU_; g_WudT[k*NX_ + j] = Wu[i]; }
    for (int i = tid; i < NX_*ND_; i += nt){ int j = i / ND_, k = i % ND_; g_WudT[(64 + k)*NX_ + j] = Wd[i]; }
    for (int i = tid; i < NY_*NX_; i += nt){ int j = i / NX_, k = i % NX_; g_WyT[k*NY_ + j] = Wy[i]; }
}

// ============================================================================
// K1: S[t,b,:] = fu + fd + bx into the X output region, plus fu/fd stats.
//     Register-tiled GEMM: CTA = 128 rows x 64 cols, thread = 8r x 4c.
//     grid = (TB/128, 4). K = 96 (64 U + 32 D), stats split at k=64.
// ============================================================================
__global__ __launch_bounds__(256, 2) void k1_fud(const float* __restrict__ U,
                                                 const float* __restrict__ D,
                                                 const float* __restrict__ bx,
                                                 const float* __restrict__ bu,
                                                 const float* __restrict__ bd,
                                                 float* __restrict__ Xout){
    __shared__ __align__(16) float uds[96*132];   // [k][r], pad 132
    __shared__ float red[24];

    const int tid = threadIdx.x;
    const long g0 = (long)blockIdx.x * 128;
    const int cb  = blockIdx.y * 64;

    for (int idx = tid; idx < 128*64; idx += 256){
        int r = idx >> 6, k = idx & 63;
        uds[k*132 + r] = U[(g0 + r)*NU_ + k];
    }
    for (int idx = tid; idx < 128*32; idx += 256){
        int r = idx >> 5, k = idx & 31;
        uds[(64 + k)*132 + r] = D[(g0 + r)*ND_ + k];
    }
    __syncthreads();

    const int r0 = (tid >> 4) * 8;
    const int c0 = cb + (tid & 15) * 4;

    ull accu[16], accd[16];
    #pragma unroll
    for (int i = 0; i < 16; i++){ accu[i] = 0ull; accd[i] = 0ull; }

    const float* wb = g_WudT + c0;

    #pragma unroll 4
    for (int k = 0; k < 64; k++){
        float4 w = *(const float4*)(wb + k*NX_);
        ull w2[4] = { pk2(w.x, w.x), pk2(w.y, w.y), pk2(w.z, w.z), pk2(w.w, w.w) };
        ulonglong2 qa = *(const ulonglong2*)&uds[k*132 + r0];
        ulonglong2 qb = *(const ulonglong2*)&uds[k*132 + r0 + 4];
        #pragma unroll
        for (int c = 0; c < 4; c++){
            accu[c*4 + 0] = fma2(qa.x, w2[c], accu[c*4 + 0]);
            accu[c*4 + 1] = fma2(qa.y, w2[c], accu[c*4 + 1]);
            accu[c*4 + 2] = fma2(qb.x, w2[c], accu[c*4 + 2]);
            accu[c*4 + 3] = fma2(qb.y, w2[c], accu[c*4 + 3]);
        }
    }
    #pragma unroll 4
    for (int k = 64; k < 96; k++){
        float4 w = *(const float4*)(wb + k*NX_);
        ull w2[4] = { pk2(w.x, w.x), pk2(w.y, w.y), pk2(w.z, w.z), pk2(w.w, w.w) };
        ulonglong2 qa = *(const ulonglong2*)&uds[k*132 + r0];
        ulonglong2 qb = *(const ulonglong2*)&uds[k*132 + r0 + 4];
        #pragma unroll
        for (int c = 0; c < 4; c++){
            accd[c*4 + 0] = fma2(qa.x, w2[c], accd[c*4 + 0]);
            accd[c*4 + 1] = fma2(qa.y, w2[c], accd[c*4 + 1]);
            accd[c*4 + 2] = fma2(qb.x, w2[c], accd[c*4 + 2]);
            accd[c*4 + 3] = fma2(qb.y, w2[c], accd[c*4 + 3]);
        }
    }

    float s0 = 0.f, s1 = 0.f, s2 = 0.f;
    float vout[8][4];
    #pragma unroll
    for (int c = 0; c < 4; c++){
        float buc = bu[c0 + c], bdc = bd[c0 + c], bxc = bx[c0 + c];
        #pragma unroll
        for (int p = 0; p < 4; p++){
            float fu0, fu1, fd0, fd1;
            upk2(accu[c*4 + p], fu0, fu1);
            upk2(accd[c*4 + p], fd0, fd1);
            fu0 += buc; fu1 += buc; fd0 += bdc; fd1 += bdc;
            s0 += fmaxf(-fu0 - 1.f, 0.f) + fmaxf(-fu1 - 1.f, 0.f);
            s1 += fmaxf( fu0 - 1.f, 0.f) + fmaxf( fu1 - 1.f, 0.f);
            s2 += fmaxf(-fd0 - 1.f, 0.f) + fmaxf(fd0 - 1.f, 0.f)
                + fmaxf(-fd1 - 1.f, 0.f) + fmaxf(fd1 - 1.f, 0.f);
            vout[2*p    ][c] = fu0 + fd0 + bxc;
            vout[2*p + 1][c] = fu1 + fd1 + bxc;
        }
    }
    #pragma unroll
    for (int rr = 0; rr < 8; rr++){
        float4 o = make_float4(vout[rr][0], vout[rr][1], vout[rr][2], vout[rr][3]);
        *(float4*)&Xout[(g0 + r0 + rr)*NX_ + c0] = o;
    }

    s0 = warp_sum(s0); s1 = warp_sum(s1); s2 = warp_sum(s2);
    int lane = tid & 31, w = tid >> 5;
    if (lane == 0){ red[w] = s0; red[8 + w] = s1; red[16 + w] = s2; }
    __syncthreads();
    if (tid == 0){
        float a = 0, b = 0, c = 0;
        #pragma unroll
        for (int i = 0; i < 8; i++){ a += red[i]; b += red[8 + i]; c += red[16 + i]; }
        atomicAdd(&g_acc[2], (double)a);
        atomicAdd(&g_acc[3], (double)b);
        atomicAdd(&g_acc[5], (double)c);
    }
}

// ============================================================================
// K2: sequential recurrence, 128 CTAs x 8 rows, 256 threads = 128 col-pairs
//     x 2 k-halves. 128KB of WxT cached in dynamic smem (rows [0,64) and
//     [128,192)); remaining half streamed from L2 with batch-16 LDG prefetch
//     interleaved with smem-fed FMA blocks.
// ============================================================================
#define K2_SMEM_BYTES ((32768 + 2048 + 2048 + 32) * 4)

__global__ __launch_bounds__(256) void k2_rec(const float* __restrict__ x0,
                                              float* __restrict__ Xout){
    extern __shared__ __align__(16) float sm[];
    float* wc  = sm;                 // 32768 floats: [half(2)][k_local(64)][j(256)]
    float* xcT = sm + 32768;         // [k][m] 256*8
    float* ps  = sm + 32768 + 2048;  // kh==1 partials, [m][j] 8*256
    float* red = sm + 32768 + 4096;  // 24 floats

    const int tid = threadIdx.x;
    const int kh  = tid >> 7;
    const int j2  = tid & 127;
    const int c0  = j2 * 2;
    const long rb = (long)blockIdx.x * 8;

    // fill weight cache: half h caches global rows [h*128, h*128+64)
    for (int idx = tid; idx < 8192; idx += 256){
        int f = idx * 4;
        int h = f >> 14;            // 0 or 1
        int rem = f & 16383;
        int kl = rem >> 8;
        int j  = rem & 255;
        *(float4*)&wc[f] = *(const float4*)&g_WxT[((h*128 + kl)*NX_) + j];
    }
    for (int idx = tid; idx < 8*NX_; idx += 256){
        int m = idx >> 8, k = idx & 255;
        xcT[k*8 + m] = x0[(rb + m)*NX_ + k];
    }
    __syncthreads();

    float sxmin = 0.f, sxmax = 0.f, sdx = 0.f;

    const float* wsbase = wc + (kh*64)*NX_ + c0;              // smem rows: kh*128 + [0,64)
    const float* wgbase = g_WxT + (kh*128 + 64)*NX_ + c0;     // gmem rows: kh*128 + [64,128)

    for (int t = 0; t < T_; t++){
        float* Srow = Xout + ((long)t*B_ + rb)*NX_;

        float2 sv[8];
        if (kh == 0){
            #pragma unroll
            for (int m = 0; m < 8; m++) sv[m] = *(const float2*)&Srow[m*NX_ + c0];
        }

        ull a0[4] = {0,0,0,0}, a1[4] = {0,0,0,0};

        #pragma unroll 1
        for (int sb = 0; sb < 4; sb++){
            // batch-16 global weight prefetch for this superblock
            float2 wg[16];
            #pragma unroll
            for (int i = 0; i < 16; i++)
                wg[i] = *(const float2*)(wgbase + (sb*16 + i)*NX_);

            // 16 smem-weight k-steps (k_local = sb*16 + i)
            #pragma unroll
            for (int i = 0; i < 16; i++){
                int k = sb*16 + i;
                float2 w = *(const float2*)(wsbase + k*NX_);
                const ulonglong2* xr = (const ulonglong2*)(xcT + (kh*128 + k)*8);
                ulonglong2 q0 = xr[0], q1 = xr[1];
                ull w20 = pk2(w.x, w.x), w21 = pk2(w.y, w.y);
                a0[0] = fma2(q0.x, w20, a0[0]); a0[1] = fma2(q0.y, w20, a0[1]);
                a0[2] = fma2(q1.x, w20, a0[2]); a0[3] = fma2(q1.y, w20, a0[3]);
                a1[0] = fma2(q0.x, w21, a1[0]); a1[1] = fma2(q0.y, w21, a1[1]);
                a1[2] = fma2(q1.x, w21, a1[2]); a1[3] = fma2(q1.y, w21, a1[3]);
            }
            // 16 global-weight k-steps (k = 64 + sb*16 + i)
            #pragma unroll
            for (int i = 0; i < 16; i++){
                int k = 64 + sb*16 + i;
                const ulonglong2* xr = (const ulonglong2*)(xcT + (kh*128 + k)*8);
                ulonglong2 q0 = xr[0], q1 = xr[1];
                ull w20 = pk2(wg[i].x, wg[i].x), w21 = pk2(wg[i].y, wg[i].y);
                a0[0] = fma2(q0.x, w20, a0[0]); a0[1] = fma2(q0.y, w20, a0[1]);
                a0[2] = fma2(q1.x, w20, a0[2]); a0[3] = fma2(q1.y, w20, a0[3]);
                a1[0] = fma2(q0.x, w21, a1[0]); a1[1] = fma2(q0.y, w21, a1[1]);
                a1[2] = fma2(q1.x, w21, a1[2]); a1[3] = fma2(q1.y, w21, a1[3]);
            }
        }

        if (kh == 1){
            #pragma unroll
            for (int p = 0; p < 4; p++){
                float v00, v01, v10, v11;
                upk2(a0[p], v00, v01);
                upk2(a1[p], v10, v11);
                *(float2*)&ps[(2*p    )*NX_ + c0] = make_float2(v00, v10);
                *(float2*)&ps[(2*p + 1)*NX_ + c0] = make_float2(v01, v11);
            }
        }
        __syncthreads();

        if (kh == 0){
            float f0[8], f1[8];
            #pragma unroll
            for (int p = 0; p < 4; p++){
                upk2(a0[p], f0[2*p], f0[2*p+1]);
                upk2(a1[p], f1[2*p], f1[2*p+1]);
            }
            float4 oa = *(const float4*)&xcT[c0*8];
            float4 ob = *(const float4*)&xcT[c0*8 + 4];
            float4 oc = *(const float4*)&xcT[(c0+1)*8];
            float4 od = *(const float4*)&xcT[(c0+1)*8 + 4];
            float oc0[8] = {oa.x, oa.y, oa.z, oa.w, ob.x, ob.y, ob.z, ob.w};
            float oc1[8] = {oc.x, oc.y, oc.z, oc.w, od.x, od.y, od.z, od.w};
            float xn0[8], xn1[8];
            #pragma unroll
            for (int m = 0; m < 8; m++){
                float2 o = *(const float2*)&ps[m*NX_ + c0];
                float v0 = f0[m] + o.x + sv[m].x;
                float v1 = f1[m] + o.y + sv[m].y;
                sxmin += fmaxf(-v0 - 1.f, 0.f) + fmaxf(-v1 - 1.f, 0.f);
                sxmax += fmaxf( v0 - 1.f, 0.f) + fmaxf( v1 - 1.f, 0.f);
                float d0 = v0 - oc0[m], d1 = v1 - oc1[m];
                sdx += d0*d0 + d1*d1;
                *(float2*)&Srow[m*NX_ + c0] = make_float2(v0, v1);
                xn0[m] = v0; xn1[m] = v1;
            }
            *(float4*)&xcT[c0*8]       = make_float4(xn0[0], xn0[1], xn0[2], xn0[3]);
            *(float4*)&xcT[c0*8 + 4]   = make_float4(xn0[4], xn0[5], xn0[6], xn0[7]);
            *(float4*)&xcT[(c0+1)*8]   = make_float4(xn1[0], xn1[1], xn1[2], xn1[3]);
            *(float4*)&xcT[(c0+1)*8+4] = make_float4(xn1[4], xn1[5], xn1[6], xn1[7]);
        }
        __syncthreads();
    }

    sxmin = warp_sum(sxmin); sxmax = warp_sum(sxmax); sdx = warp_sum(sdx);
    int lane = tid & 31, w = tid >> 5;
    if (lane == 0){ red[w] = sxmin; red[8 + w] = sxmax; red[16 + w] = sdx; }
    __syncthreads();
    if (tid == 0){
        float a = 0, b = 0, c = 0;
        #pragma unroll
        for (int i = 0; i < 8; i++){ a += red[i]; b += red[8 + i]; c += red[16 + i]; }
        atomicAdd(&g_acc[0], (double)a);
        atomicAdd(&g_acc[1], (double)b);
        atomicAdd(&g_acc[4], (double)c);
    }
}

// ============================================================================
// K3: Y = X @ Wy^T + by. Register-tiled: CTA = 128 rows x 64 cols (full NY),
//     thread = 8r x 4c, K = 256 staged in 4 chunks of 64.
// ============================================================================
__global__ __launch_bounds__(256) void k3_y(const float* __restrict__ Xout,
                                            const float* __restrict__ by,
                                            float* __restrict__ Yout){
    __shared__ __align__(16) float xs[64*132];
    const int tid = threadIdx.x;
    const long g0 = (long)blockIdx.x * 128;
    const int r0 = (tid >> 4) * 8;
    const int c0 = (tid & 15) * 4;

    ull acc[16];
    #pragma unroll
    for (int i = 0; i < 16; i++) acc[i] = 0ull;

    for (int ch = 0; ch < 4; ch++){
        if (ch) __syncthreads();
        for (int idx = tid; idx < 128*64; idx += 256){
            int r = idx >> 6, k = idx & 63;
            xs[k*132 + r] = Xout[(g0 + r)*NX_ + ch*64 + k];
        }
        __syncthreads();

        const float* wb = g_WyT + (ch*64)*NY_ + c0;
        #pragma unroll 4
        for (int k = 0; k < 64; k++){
            float4 w = *(const float4*)(wb + k*NY_);
            ull w2[4] = { pk2(w.x, w.x), pk2(w.y, w.y), pk2(w.z, w.z), pk2(w.w, w.w) };
            ulonglong2 qa = *(const ulonglong2*)&xs[k*132 + r0];
            ulonglong2 qb = *(const ulonglong2*)&xs[k*132 + r0 + 4];
            #pragma unroll
            for (int c = 0; c < 4; c++){
                acc[c*4 + 0] = fma2(qa.x, w2[c], acc[c*4 + 0]);
                acc[c*4 + 1] = fma2(qa.y, w2[c], acc[c*4 + 1]);
                acc[c*4 + 2] = fma2(qb.x, w2[c], acc[c*4 + 2]);
                acc[c*4 + 3] = fma2(qb.y, w2[c], acc[c*4 + 3]);
            }
        }
    }

    float byv[4] = { by[c0], by[c0+1], by[c0+2], by[c0+3] };
    float vout[8][4];
    #pragma unroll
    for (int c = 0; c < 4; c++){
        #pragma unroll
        for (int p = 0; p < 4; p++){
            float lo, hi;
            upk2(acc[c*4 + p], lo, hi);
            vout[2*p    ][c] = lo + byv[c];
            vout[2*p + 1][c] = hi + byv[c];
        }
    }
    #pragma unroll
    for (int rr = 0; rr < 8; rr++){
        float4 o = make_float4(vout[rr][0], vout[rr][1], vout[rr][2], vout[rr][3]);
        *(float4*)&Yout[(g0 + r0 + rr)*NY_ + c0] = o;
    }
}

// ============================================================================
// K4: finalize reg_error = Q * sum(stat means); dx_u == sumin+sumax.
// ============================================================================
__global__ void k4_fin(float* __restrict__ out_reg){
    double inv = 1.0 / ((double)T_ * (double)B_ * (double)NX_);
    double s = g_acc[0] + g_acc[1] + 2.0*(g_acc[2] + g_acc[3]) + g_acc[4] + g_acc[5];
    *out_reg = (float)(0.2 * s * inv);
}

extern "C" void kernel_launch(void* const* d_in, const int* in_sizes, int n_in,
                              void* d_out, int out_size){
    const float* x  = (const float*)d_in[0];
    const float* U  = (const float*)d_in[1];
    const float* D  = (const float*)d_in[2];
    const float* Wx = (const float*)d_in[3];
    const float* bx = (const float*)d_in[4];
    const float* Wu = (const float*)d_in[5];
    const float* bu = (const float*)d_in[6];
    const float* Wd = (const float*)d_in[7];
    const float* bd = (const float*)d_in[8];
    const float* Wy = (const float*)d_in[9];
    const float* by = (const float*)d_in[10];

    float* out  = (float*)d_out;
    float* Xout = out;
    float* Yout = out + (size_t)TB_ * NX_;
    float* Rout = out + (size_t)TB_ * NX_ + (size_t)TB_ * NY_;

    cudaFuncSetAttribute(k2_rec, cudaFuncAttributeMaxDynamicSharedMemorySize,
                         K2_SMEM_BYTES);

    k0_prep<<<256, 256>>>(Wx, Wu, Wd, Wy);
    k1_fud<<<dim3(TB_/128, 4), 256>>>(U, D, bx, bu, bd, Xout);
    k2_rec<<<B_/8, 256, K2_SMEM_BYTES>>>(x, Xout);
    k3_y<<<TB_/128, 256>>>(Xout, by, Yout);
    k4_fin<<<1, 1>>>(Rout);
}

// round 8
// speedup vs baseline: 2.3836x; 1.1049x over previous
#include <cuda_runtime.h>

#define T_  256
#define B_  1024
#define NX_ 256
#define NY_ 64
#define NU_ 64
#define ND_ 32
#define TB_ (T_*B_)

typedef unsigned long long ull;

// ---- device globals: transposed weights + stat accumulators (no allocs) ----
__device__ float  g_WxT [NX_*NX_];   // [k][j]
__device__ float  g_WudT[96*NX_];    // [k][j], k<64 = Wu-k, k>=64 = Wd-(k-64)
__device__ float  g_WyT [NX_*NY_];   // [k][j]
__device__ double g_acc[6];          // 0:sxmin 1:sxmax 2:sumin 3:sumax 4:sdx 5:dxd

// ---- packed fp32x2 helpers (Blackwell dual-FP32 pipe) ----
__device__ __forceinline__ ull pk2(float lo, float hi){
    ull r;
    asm("mov.b64 %0, {%1, %2};" : "=l"(r) : "f"(lo), "f"(hi));
    return r;
}
__device__ __forceinline__ void upk2(ull v, float& lo, float& hi){
    asm("mov.b64 {%0, %1}, %2;" : "=f"(lo), "=f"(hi) : "l"(v));
}
__device__ __forceinline__ ull fma2(ull a, ull b, ull c){
    ull d;
    asm("fma.rn.f32x2 %0, %1, %2, %3;" : "=l"(d) : "l"(a), "l"(b), "l"(c));
    return d;
}
__device__ __forceinline__ float warp_sum(float v){
    #pragma unroll
    for (int o = 16; o > 0; o >>= 1) v += __shfl_down_sync(0xffffffffu, v, o);
    return v;
}

// ============================================================================
// K0: build transposed/fused weight layouts, zero accumulators
// ============================================================================
__global__ void k0_prep(const float* __restrict__ Wx, const float* __restrict__ Wu,
                        const float* __restrict__ Wd, const float* __restrict__ Wy){
    int tid = blockIdx.x * blockDim.x + threadIdx.x;
    int nt  = gridDim.x * blockDim.x;
    if (blockIdx.x == 0 && threadIdx.x < 6) g_acc[threadIdx.x] = 0.0;
    for (int i = tid; i < NX_*NX_; i += nt){ int j = i / NX_, k = i % NX_; g_WxT[k*NX_ + j] = Wx[i]; }
    for (int i = tid; i < NX_*NU_; i += nt){ int j = i / NU_, k = i % NU_; g_WudT[k*NX_ + j] = Wu[i]; }
    for (int i = tid; i < NX_*ND_; i += nt){ int j = i / ND_, k = i % ND_; g_WudT[(64 + k)*NX_ + j] = Wd[i]; }
    for (int i = tid; i < NY_*NX_; i += nt){ int j = i / NX_, k = i % NX_; g_WyT[k*NY_ + j] = Wy[i]; }
}

// ============================================================================
// K1: S[t,b,:] = fu + fd + bx into the X output region, plus fu/fd stats.
//     Register-tiled GEMM: CTA = 128 rows x 64 cols, thread = 8r x 4c.
// ============================================================================
__global__ __launch_bounds__(256, 2) void k1_fud(const float* __restrict__ U,
                                                 const float* __restrict__ D,
                                                 const float* __restrict__ bx,
                                                 const float* __restrict__ bu,
                                                 const float* __restrict__ bd,
                                                 float* __restrict__ Xout){
    __shared__ __align__(16) float uds[96*132];
    __shared__ float red[24];

    const int tid = threadIdx.x;
    const long g0 = (long)blockIdx.x * 128;
    const int cb  = blockIdx.y * 64;

    for (int idx = tid; idx < 128*64; idx += 256){
        int r = idx >> 6, k = idx & 63;
        uds[k*132 + r] = U[(g0 + r)*NU_ + k];
    }
    for (int idx = tid; idx < 128*32; idx += 256){
        int r = idx >> 5, k = idx & 31;
        uds[(64 + k)*132 + r] = D[(g0 + r)*ND_ + k];
    }
    __syncthreads();

    const int r0 = (tid >> 4) * 8;
    const int c0 = cb + (tid & 15) * 4;

    ull accu[16], accd[16];
    #pragma unroll
    for (int i = 0; i < 16; i++){ accu[i] = 0ull; accd[i] = 0ull; }

    const float* wb = g_WudT + c0;

    #pragma unroll 4
    for (int k = 0; k < 64; k++){
        float4 w = *(const float4*)(wb + k*NX_);
        ull w2[4] = { pk2(w.x, w.x), pk2(w.y, w.y), pk2(w.z, w.z), pk2(w.w, w.w) };
        ulonglong2 qa = *(const ulonglong2*)&uds[k*132 + r0];
        ulonglong2 qb = *(const ulonglong2*)&uds[k*132 + r0 + 4];
        #pragma unroll
        for (int c = 0; c < 4; c++){
            accu[c*4 + 0] = fma2(qa.x, w2[c], accu[c*4 + 0]);
            accu[c*4 + 1] = fma2(qa.y, w2[c], accu[c*4 + 1]);
            accu[c*4 + 2] = fma2(qb.x, w2[c], accu[c*4 + 2]);
            accu[c*4 + 3] = fma2(qb.y, w2[c], accu[c*4 + 3]);
        }
    }
    #pragma unroll 4
    for (int k = 64; k < 96; k++){
        float4 w = *(const float4*)(wb + k*NX_);
        ull w2[4] = { pk2(w.x, w.x), pk2(w.y, w.y), pk2(w.z, w.z), pk2(w.w, w.w) };
        ulonglong2 qa = *(const ulonglong2*)&uds[k*132 + r0];
        ulonglong2 qb = *(const ulonglong2*)&uds[k*132 + r0 + 4];
        #pragma unroll
        for (int c = 0; c < 4; c++){
            accd[c*4 + 0] = fma2(qa.x, w2[c], accd[c*4 + 0]);
            accd[c*4 + 1] = fma2(qa.y, w2[c], accd[c*4 + 1]);
            accd[c*4 + 2] = fma2(qb.x, w2[c], accd[c*4 + 2]);
            accd[c*4 + 3] = fma2(qb.y, w2[c], accd[c*4 + 3]);
        }
    }

    float s0 = 0.f, s1 = 0.f, s2 = 0.f;
    float vout[8][4];
    #pragma unroll
    for (int c = 0; c < 4; c++){
        float buc = bu[c0 + c], bdc = bd[c0 + c], bxc = bx[c0 + c];
        #pragma unroll
        for (int p = 0; p < 4; p++){
            float fu0, fu1, fd0, fd1;
            upk2(accu[c*4 + p], fu0, fu1);
            upk2(accd[c*4 + p], fd0, fd1);
            fu0 += buc; fu1 += buc; fd0 += bdc; fd1 += bdc;
            s0 += fmaxf(-fu0 - 1.f, 0.f) + fmaxf(-fu1 - 1.f, 0.f);
            s1 += fmaxf( fu0 - 1.f, 0.f) + fmaxf( fu1 - 1.f, 0.f);
            s2 += fmaxf(-fd0 - 1.f, 0.f) + fmaxf(fd0 - 1.f, 0.f)
                + fmaxf(-fd1 - 1.f, 0.f) + fmaxf(fd1 - 1.f, 0.f);
            vout[2*p    ][c] = fu0 + fd0 + bxc;
            vout[2*p + 1][c] = fu1 + fd1 + bxc;
        }
    }
    #pragma unroll
    for (int rr = 0; rr < 8; rr++){
        float4 o = make_float4(vout[rr][0], vout[rr][1], vout[rr][2], vout[rr][3]);
        *(float4*)&Xout[(g0 + r0 + rr)*NX_ + c0] = o;
    }

    s0 = warp_sum(s0); s1 = warp_sum(s1); s2 = warp_sum(s2);
    int lane = tid & 31, w = tid >> 5;
    if (lane == 0){ red[w] = s0; red[8 + w] = s1; red[16 + w] = s2; }
    __syncthreads();
    if (tid == 0){
        float a = 0, b = 0, c = 0;
        #pragma unroll
        for (int i = 0; i < 8; i++){ a += red[i]; b += red[8 + i]; c += red[16 + i]; }
        atomicAdd(&g_acc[2], (double)a);
        atomicAdd(&g_acc[3], (double)b);
        atomicAdd(&g_acc[5], (double)c);
    }
}

// ============================================================================
// K2: sequential recurrence. 128 CTAs x 8 rows, 256 threads = 128 col-pairs
//     x 2 k-halves. 192KB (3/4) of WxT in smem; remaining 64 rows streamed
//     with batch-16 prefetch covered by 48 smem-fed k-steps. Symmetric
//     epilogue: both halves write partials; each thread then owns one column.
// ============================================================================
// floats: wc 2*96*256 = 49152 | xcT 2048 | ps 2*8*256 = 4096 | red 24
#define K2_SMEM_FLOATS (49152 + 2048 + 4096 + 32)
#define K2_SMEM_BYTES  (K2_SMEM_FLOATS * 4)

__global__ __launch_bounds__(256, 1) void k2_rec(const float* __restrict__ x0,
                                                 float* __restrict__ Xout){
    extern __shared__ __align__(16) float sm[];
    float* wc  = sm;                       // [half][kl<96][j<256]
    float* xcT = sm + 49152;               // [k][m]
    float* ps  = sm + 49152 + 2048;        // [half][m][j]
    float* red = sm + 49152 + 2048 + 4096;

    const int tid = threadIdx.x;
    const int kh  = tid >> 7;
    const int c0  = (tid & 127) * 2;
    const long rb = (long)blockIdx.x * 8;

    // cache weight rows kh*128 + [0,96) per half
    for (int idx = tid; idx < 12288; idx += 256){
        int f = idx * 4;
        int h   = f / 24576;
        int rem = f % 24576;
        int kl  = rem >> 8;
        int j   = rem & 255;
        *(float4*)&wc[f] = *(const float4*)&g_WxT[(h*128 + kl)*NX_ + j];
    }
    for (int idx = tid; idx < 8*NX_; idx += 256){
        int m = idx >> 8, k = idx & 255;
        xcT[k*8 + m] = x0[(rb + m)*NX_ + k];
    }
    __syncthreads();

    float sxmin = 0.f, sxmax = 0.f, sdx = 0.f;

    const float* wsbase = wc + (kh*96)*NX_ + c0;             // smem rows kh*128+[0,96)
    const float* wgbase = g_WxT + (kh*128 + 96)*NX_ + c0;    // gmem rows kh*128+[96,128)
    const float* xbase  = xcT + (kh*128)*8;
    float* psme = ps + kh*2048;

    for (int t = 0; t < T_; t++){
        float* Srow = Xout + ((long)t*B_ + rb)*NX_;

        // own-column S values (consumed in epilogue, latency hidden by mainloop)
        float sv[8];
        #pragma unroll
        for (int m = 0; m < 8; m++) sv[m] = Srow[m*NX_ + tid];

        ull a0[4] = {0,0,0,0}, a1[4] = {0,0,0,0};
        float2 wg[16];

        // P0: prefetch global rows [96,112)
        #pragma unroll
        for (int i = 0; i < 16; i++) wg[i] = *(const float2*)(wgbase + i*NX_);

        // S0: smem k-steps [0,48)
        #pragma unroll 8
        for (int k = 0; k < 48; k++){
            float2 w = *(const float2*)(wsbase + k*NX_);
            const ulonglong2* xr = (const ulonglong2*)(xbase + k*8);
            ulonglong2 q0 = xr[0], q1 = xr[1];
            ull w20 = pk2(w.x, w.x), w21 = pk2(w.y, w.y);
            a0[0] = fma2(q0.x, w20, a0[0]); a0[1] = fma2(q0.y, w20, a0[1]);
            a0[2] = fma2(q1.x, w20, a0[2]); a0[3] = fma2(q1.y, w20, a0[3]);
            a1[0] = fma2(q0.x, w21, a1[0]); a1[1] = fma2(q0.y, w21, a1[1]);
            a1[2] = fma2(q1.x, w21, a1[2]); a1[3] = fma2(q1.y, w21, a1[3]);
        }
        // C0: consume global k [96,112)
        #pragma unroll
        for (int i = 0; i < 16; i++){
            const ulonglong2* xr = (const ulonglong2*)(xbase + (96 + i)*8);
            ulonglong2 q0 = xr[0], q1 = xr[1];
            ull w20 = pk2(wg[i].x, wg[i].x), w21 = pk2(wg[i].y, wg[i].y);
            a0[0] = fma2(q0.x, w20, a0[0]); a0[1] = fma2(q0.y, w20, a0[1]);
            a0[2] = fma2(q1.x, w20, a0[2]); a0[3] = fma2(q1.y, w20, a0[3]);
            a1[0] = fma2(q0.x, w21, a1[0]); a1[1] = fma2(q0.y, w21, a1[1]);
            a1[2] = fma2(q1.x, w21, a1[2]); a1[3] = fma2(q1.y, w21, a1[3]);
        }
        // P1: prefetch global rows [112,128)
        #pragma unroll
        for (int i = 0; i < 16; i++) wg[i] = *(const float2*)(wgbase + (16 + i)*NX_);

        // S1: smem k-steps [48,96)
        #pragma unroll 8
        for (int k = 48; k < 96; k++){
            float2 w = *(const float2*)(wsbase + k*NX_);
            const ulonglong2* xr = (const ulonglong2*)(xbase + k*8);
            ulonglong2 q0 = xr[0], q1 = xr[1];
            ull w20 = pk2(w.x, w.x), w21 = pk2(w.y, w.y);
            a0[0] = fma2(q0.x, w20, a0[0]); a0[1] = fma2(q0.y, w20, a0[1]);
            a0[2] = fma2(q1.x, w20, a0[2]); a0[3] = fma2(q1.y, w20, a0[3]);
            a1[0] = fma2(q0.x, w21, a1[0]); a1[1] = fma2(q0.y, w21, a1[1]);
            a1[2] = fma2(q1.x, w21, a1[2]); a1[3] = fma2(q1.y, w21, a1[3]);
        }
        // C1: consume global k [112,128)
        #pragma unroll
        for (int i = 0; i < 16; i++){
            const ulonglong2* xr = (const ulonglong2*)(xbase + (112 + i)*8);
            ulonglong2 q0 = xr[0], q1 = xr[1];
            ull w20 = pk2(wg[i].x, wg[i].x), w21 = pk2(wg[i].y, wg[i].y);
            a0[0] = fma2(q0.x, w20, a0[0]); a0[1] = fma2(q0.y, w20, a0[1]);
            a0[2] = fma2(q1.x, w20, a0[2]); a0[3] = fma2(q1.y, w20, a0[3]);
            a1[0] = fma2(q0.x, w21, a1[0]); a1[1] = fma2(q0.y, w21, a1[1]);
            a1[2] = fma2(q1.x, w21, a1[2]); a1[3] = fma2(q1.y, w21, a1[3]);
        }

        // both halves dump partials: ps[kh][m][c0..c0+1]
        {
            float f0[8], f1[8];
            #pragma unroll
            for (int p = 0; p < 4; p++){
                upk2(a0[p], f0[2*p], f0[2*p+1]);
                upk2(a1[p], f1[2*p], f1[2*p+1]);
            }
            #pragma unroll
            for (int m = 0; m < 8; m++)
                *(float2*)&psme[m*NX_ + c0] = make_float2(f0[m], f1[m]);
        }
        __syncthreads();

        // symmetric epilogue: thread owns column j = tid, rows 0..7
        {
            float4 xo0 = *(const float4*)&xcT[tid*8];
            float4 xo1 = *(const float4*)&xcT[tid*8 + 4];
            float xold[8] = {xo0.x, xo0.y, xo0.z, xo0.w, xo1.x, xo1.y, xo1.z, xo1.w};
            float xn[8];
            #pragma unroll
            for (int m = 0; m < 8; m++){
                float v = ps[m*NX_ + tid] + ps[2048 + m*NX_ + tid] + sv[m];
                sxmin += fmaxf(-v - 1.f, 0.f);
                sxmax += fmaxf( v - 1.f, 0.f);
                float d = v - xold[m];
                sdx += d*d;
                Srow[m*NX_ + tid] = v;
                xn[m] = v;
            }
            *(float4*)&xcT[tid*8]     = make_float4(xn[0], xn[1], xn[2], xn[3]);
            *(float4*)&xcT[tid*8 + 4] = make_float4(xn[4], xn[5], xn[6], xn[7]);
        }
        __syncthreads();
    }

    sxmin = warp_sum(sxmin); sxmax = warp_sum(sxmax); sdx = warp_sum(sdx);
    int lane = tid & 31, w = tid >> 5;
    if (lane == 0){ red[w] = sxmin; red[8 + w] = sxmax; red[16 + w] = sdx; }
    __syncthreads();
    if (tid == 0){
        float a = 0, b = 0, c = 0;
        #pragma unroll
        for (int i = 0; i < 8; i++){ a += red[i]; b += red[8 + i]; c += red[16 + i]; }
        atomicAdd(&g_acc[0], (double)a);
        atomicAdd(&g_acc[1], (double)b);
        atomicAdd(&g_acc[4], (double)c);
    }
}

// ============================================================================
// K3: Y = X @ Wy^T + by. Register-tiled: CTA = 128 rows x 64 cols (full NY),
//     thread = 8r x 4c, K = 256 staged in 4 chunks of 64. occ target 4 CTAs.
// ============================================================================
__global__ __launch_bounds__(256, 4) void k3_y(const float* __restrict__ Xout,
                                               const float* __restrict__ by,
                                               float* __restrict__ Yout){
    __shared__ __align__(16) float xs[64*132];
    const int tid = threadIdx.x;
    const long g0 = (long)blockIdx.x * 128;
    const int r0 = (tid >> 4) * 8;
    const int c0 = (tid & 15) * 4;

    ull acc[16];
    #pragma unroll
    for (int i = 0; i < 16; i++) acc[i] = 0ull;

    for (int ch = 0; ch < 4; ch++){
        if (ch) __syncthreads();
        for (int idx = tid; idx < 128*64; idx += 256){
            int r = idx >> 6, k = idx & 63;
            xs[k*132 + r] = Xout[(g0 + r)*NX_ + ch*64 + k];
        }
        __syncthreads();

        const float* wb = g_WyT + (ch*64)*NY_ + c0;
        #pragma unroll 4
        for (int k = 0; k < 64; k++){
            float4 w = *(const float4*)(wb + k*NY_);
            ull w2[4] = { pk2(w.x, w.x), pk2(w.y, w.y), pk2(w.z, w.z), pk2(w.w, w.w) };
            ulonglong2 qa = *(const ulonglong2*)&xs[k*132 + r0];
            ulonglong2 qb = *(const ulonglong2*)&xs[k*132 + r0 + 4];
            #pragma unroll
            for (int c = 0; c < 4; c++){
                acc[c*4 + 0] = fma2(qa.x, w2[c], acc[c*4 + 0]);
                acc[c*4 + 1] = fma2(qa.y, w2[c], acc[c*4 + 1]);
                acc[c*4 + 2] = fma2(qb.x, w2[c], acc[c*4 + 2]);
                acc[c*4 + 3] = fma2(qb.y, w2[c], acc[c*4 + 3]);
            }
        }
    }

    float byv[4] = { by[c0], by[c0+1], by[c0+2], by[c0+3] };
    float vout[8][4];
    #pragma unroll
    for (int c = 0; c < 4; c++){
        #pragma unroll
        for (int p = 0; p < 4; p++){
            float lo, hi;
            upk2(acc[c*4 + p], lo, hi);
            vout[2*p    ][c] = lo + byv[c];
            vout[2*p + 1][c] = hi + byv[c];
        }
    }
    #pragma unroll
    for (int rr = 0; rr < 8; rr++){
        float4 o = make_float4(vout[rr][0], vout[rr][1], vout[rr][2], vout[rr][3]);
        *(float4*)&Yout[(g0 + r0 + rr)*NY_ + c0] = o;
    }
}

// ============================================================================
// K4: finalize reg_error = Q * sum(stat means); dx_u == sumin+sumax.
// ============================================================================
__global__ void k4_fin(float* __restrict__ out_reg){
    double inv = 1.0 / ((double)T_ * (double)B_ * (double)NX_);
    double s = g_acc[0] + g_acc[1] + 2.0*(g_acc[2] + g_acc[3]) + g_acc[4] + g_acc[5];
    *out_reg = (float)(0.2 * s * inv);
}

extern "C" void kernel_launch(void* const* d_in, const int* in_sizes, int n_in,
                              void* d_out, int out_size){
    const float* x  = (const float*)d_in[0];
    const float* U  = (const float*)d_in[1];
    const float* D  = (const float*)d_in[2];
    const float* Wx = (const float*)d_in[3];
    const float* bx = (const float*)d_in[4];
    const float* Wu = (const float*)d_in[5];
    const float* bu = (const float*)d_in[6];
    const float* Wd = (const float*)d_in[7];
    const float* bd = (const float*)d_in[8];
    const float* Wy = (const float*)d_in[9];
    const float* by = (const float*)d_in[10];

    float* out  = (float*)d_out;
    float* Xout = out;
    float* Yout = out + (size_t)TB_ * NX_;
    float* Rout = out + (size_t)TB_ * NX_ + (size_t)TB_ * NY_;

    cudaFuncSetAttribute(k2_rec, cudaFuncAttributeMaxDynamicSharedMemorySize,
                         K2_SMEM_BYTES);

    k0_prep<<<256, 256>>>(Wx, Wu, Wd, Wy);
    k1_fud<<<dim3(TB_/128, 4), 256>>>(U, D, bx, bu, bd, Xout);
    k2_rec<<<B_/8, 256, K2_SMEM_BYTES>>>(x, Xout);
    k3_y<<<TB_/128, 256>>>(Xout, by, Yout);
    k4_fin<<<1, 1>>>(Rout);
}